// round 13
// baseline (speedup 1.0000x reference)
#include <cuda_runtime.h>
#include <cuda_bf16.h>
#include <cstdint>

#define DIM_K 4096
#define DIM_N 4096
#define MR    8192

__device__ __nv_bfloat16 g_qab [(size_t)MR * DIM_K];     // bf16 quantized lhs [MR,K]
__device__ __nv_bfloat16 g_qbTb[(size_t)DIM_N * DIM_K];  // bf16 quantized rhs^T [N,K]
__device__ float    g_sl[MR];
__device__ unsigned g_amax[DIM_N];

// ---------------- helpers ----------------
__device__ __forceinline__ uint32_t smem_u32(const void* p) {
    uint32_t a;
    asm("{ .reg .u64 t; cvta.to.shared.u64 t, %1; cvt.u32.u64 %0, t; }" : "=r"(a) : "l"(p));
    return a;
}
__device__ __forceinline__ void cp16(uint32_t dst, const void* src) {
    asm volatile("cp.async.cg.shared.global [%0], [%1], 16;" :: "r"(dst), "l"(src) : "memory");
}
__device__ __forceinline__ void ldm_x4(uint32_t* r, uint32_t addr) {
    asm volatile("ldmatrix.sync.aligned.m8n8.x4.shared.b16 {%0,%1,%2,%3}, [%4];"
                 : "=r"(r[0]), "=r"(r[1]), "=r"(r[2]), "=r"(r[3]) : "r"(addr));
}
__device__ __forceinline__ void mma_bf(float* c, const uint32_t* a, uint32_t b0, uint32_t b1) {
    asm volatile("mma.sync.aligned.m16n8k16.row.col.f32.bf16.bf16.f32 "
                 "{%0,%1,%2,%3}, {%4,%5,%6,%7}, {%8,%9}, {%0,%1,%2,%3};"
                 : "+f"(c[0]), "+f"(c[1]), "+f"(c[2]), "+f"(c[3])
                 : "r"(a[0]), "r"(a[1]), "r"(a[2]), "r"(a[3]), "r"(b0), "r"(b1));
}
__device__ __forceinline__ float qv(float x, float sc) {
    return fminf(fmaxf(rintf(x / sc), -127.f), 127.f);
}
__device__ __forceinline__ float col_scale(int n) {
    float am = __uint_as_float(g_amax[n]);
    return (am > 0.f) ? (am / 127.f) : 1.f;
}

// ---------------- K1: quantize lhs rows -> bf16 ----------------
__global__ __launch_bounds__(256) void k_quant_lhs(const float* __restrict__ lhs) {
    int row = blockIdx.x;
    const float4* src = reinterpret_cast<const float4*>(lhs) + (size_t)row * (DIM_K / 4);
    int t = threadIdx.x;
    float4 v[4];
    float amax = 0.f;
#pragma unroll
    for (int j = 0; j < 4; j++) {
        v[j] = src[t + j * 256];
        amax = fmaxf(amax, fmaxf(fmaxf(fabsf(v[j].x), fabsf(v[j].y)),
                                 fmaxf(fabsf(v[j].z), fabsf(v[j].w))));
    }
#pragma unroll
    for (int o = 16; o > 0; o >>= 1)
        amax = fmaxf(amax, __shfl_xor_sync(0xffffffffu, amax, o));
    __shared__ float wmax[8];
    __shared__ float sres;
    if ((t & 31) == 0) wmax[t >> 5] = amax;
    __syncthreads();
    if (t == 0) {
        float m = wmax[0];
#pragma unroll
        for (int j = 1; j < 8; j++) m = fmaxf(m, wmax[j]);
        float sc = (m > 0.f) ? (m / 127.f) : 1.f;
        sres = sc;
        g_sl[row] = sc;
    }
    __syncthreads();
    float sc = sres;
    uint2* dst = reinterpret_cast<uint2*>(g_qab + (size_t)row * DIM_K);
#pragma unroll
    for (int j = 0; j < 4; j++) {
        __nv_bfloat162 h0 = __floats2bfloat162_rn(qv(v[j].x, sc), qv(v[j].y, sc));
        __nv_bfloat162 h1 = __floats2bfloat162_rn(qv(v[j].z, sc), qv(v[j].w, sc));
        uint2 u;
        u.x = *reinterpret_cast<unsigned*>(&h0);
        u.y = *reinterpret_cast<unsigned*>(&h1);
        dst[t + j * 256] = u;
    }
}

// ---------------- K2: rhs amax + transpose-quantize -> bf16 ----------------
__global__ __launch_bounds__(256) void k_rhs_amax(const float* __restrict__ rhs) {
    int n = blockIdx.x * 256 + threadIdx.x;
    int k0 = blockIdx.y * 128;
    const float* p = rhs + (size_t)k0 * DIM_N + n;
    float amax = 0.f;
#pragma unroll 4
    for (int kk = 0; kk < 128; kk++)
        amax = fmaxf(amax, fabsf(p[(size_t)kk * DIM_N]));
    atomicMax(&g_amax[n], __float_as_uint(amax));
}

__global__ __launch_bounds__(256) void k_quant_rhs_t(const float* __restrict__ rhs) {
    __shared__ float tile[64][65];
    int n0 = blockIdx.x * 64, k0 = blockIdx.y * 64;
    int t = threadIdx.x;
    int c = t & 63, r0 = t >> 6;
    float sc = col_scale(n0 + c);
#pragma unroll
    for (int e = 0; e < 16; e++) {
        int r = r0 + e * 4;
        float x = rhs[(size_t)(k0 + r) * DIM_N + n0 + c];
        tile[c][r] = qv(x, sc);
    }
    __syncthreads();
    int rn = t >> 2, c16 = t & 3;
    uint32_t pb[8];
#pragma unroll
    for (int g = 0; g < 8; g++) {
        __nv_bfloat162 h = __floats2bfloat162_rn(tile[rn][c16 * 16 + g * 2],
                                                 tile[rn][c16 * 16 + g * 2 + 1]);
        pb[g] = *reinterpret_cast<unsigned*>(&h);
    }
    __nv_bfloat16* db = g_qbTb + (size_t)(n0 + rn) * DIM_K + k0 + c16 * 16;
    uint4 w0, w1;
    w0.x = pb[0]; w0.y = pb[1]; w0.z = pb[2]; w0.w = pb[3];
    w1.x = pb[4]; w1.y = pb[5]; w1.z = pb[6]; w1.w = pb[7];
    *reinterpret_cast<uint4*>(db) = w0;
    *reinterpret_cast<uint4*>(db + 8) = w1;
}

// ---------------- K3: bf16 GEMM, 256x128 tile, 512 thr, A-frag pipelined ----------------
#define BM 256
#define BN 128
#define GT 512
#define ROWB 144
#define BKB 128
#define STAGES 4
#define A_BYTES (BM * ROWB)
#define B_BYTES (BN * ROWB)
#define STAGE_BYTES (A_BYTES + B_BYTES)
#define SMEM_GEMM (STAGES * STAGE_BYTES)
#define NCHUNK (DIM_K * 2 / BKB)

__device__ __forceinline__ void load_stage(uint32_t sbase, int t,
                                           const char* gA, const char* gB,
                                           size_t kByte) {
    const size_t rstride = (size_t)DIM_K * 2;
#pragma unroll
    for (int j = 0; j < 4; j++) {
        int c = t + j * GT;
        int r = c >> 3, q = c & 7;
        cp16(sbase + r * ROWB + q * 16, gA + (size_t)r * rstride + kByte + q * 16);
    }
#pragma unroll
    for (int j = 0; j < 2; j++) {
        int c = t + j * GT;
        int r = c >> 3, q = c & 7;
        cp16(sbase + A_BYTES + r * ROWB + q * 16, gB + (size_t)r * rstride + kByte + q * 16);
    }
}

__global__ __launch_bounds__(GT, 1) void k_gemm(float* __restrict__ out) {
    extern __shared__ __align__(128) uint8_t smem[];
    const uint32_t sb = smem_u32(smem);
    const int t = threadIdx.x;
    const int w = t >> 5, l = t & 31;
    const int n0 = blockIdx.x * BN;
    const int m0 = blockIdx.y * BM;
    const int wm = w & 3, wn = w >> 2;       // warp grid 4x4
    const int m_off = wm * 64, n_off = wn * 32;

    const char* gA = (const char*)(g_qab + (size_t)m0 * DIM_K);
    const char* gB = (const char*)(g_qbTb + (size_t)n0 * DIM_K);

    float c[4][4][4];                        // 64 accum regs
#pragma unroll
    for (int mi = 0; mi < 4; mi++)
#pragma unroll
        for (int ni = 0; ni < 4; ni++)
#pragma unroll
            for (int e = 0; e < 4; e++) c[mi][ni][e] = 0.f;

    const int lrow = (l & 7) + ((l >> 3) & 1) * 8;
    const int lcol = (l >> 4) * 16;
    const uint32_t aBase = (uint32_t)((m_off + lrow) * ROWB + lcol);
    const uint32_t bBase = (uint32_t)(A_BYTES + (n_off + lrow) * ROWB + lcol);

#pragma unroll
    for (int p = 0; p < STAGES - 1; p++) {
        load_stage(sb + p * STAGE_BYTES, t, gA, gB, (size_t)p * BKB);
        asm volatile("cp.async.commit_group;" ::: "memory");
    }

    uint32_t a[2][4][4];                     // A frags double-buffered across ks

    for (int i = 0; i < NCHUNK; i++) {
        asm volatile("cp.async.wait_group 2;" ::: "memory");
        __syncthreads();

        const uint32_t stA = sb + (uint32_t)(i & 3) * STAGE_BYTES + aBase;
        const uint32_t stB = sb + (uint32_t)(i & 3) * STAGE_BYTES + bBase;

        // prime A for ks=0
#pragma unroll
        for (int mi = 0; mi < 4; mi++)
            ldm_x4(a[0][mi], stA + mi * (16 * ROWB));

        if (i + STAGES - 1 < NCHUNK)
            load_stage(sb + ((i + STAGES - 1) & 3) * STAGE_BYTES, t, gA, gB,
                       (size_t)(i + STAGES - 1) * BKB);
        asm volatile("cp.async.commit_group;" ::: "memory");

#pragma unroll
        for (int ks = 0; ks < 4; ks++) {
            const int cur = ks & 1, nxt = cur ^ 1;
            // B frags for this ks (issued first so wait drains during A-prefetch issue)
            uint32_t b0[4], b1[4];
            ldm_x4(b0, stB + ks * 32);
            ldm_x4(b1, stB + 16 * ROWB + ks * 32);
            // prefetch next ks's A frags (overlaps with this ks's MMAs)
            if (ks < 3) {
#pragma unroll
                for (int mi = 0; mi < 4; mi++)
                    ldm_x4(a[nxt][mi], stA + mi * (16 * ROWB) + (ks + 1) * 32);
            }
#pragma unroll
            for (int mi = 0; mi < 4; mi++) {
                mma_bf(c[mi][0], a[cur][mi], b0[0], b0[2]);
                mma_bf(c[mi][1], a[cur][mi], b0[1], b0[3]);
                mma_bf(c[mi][2], a[cur][mi], b1[0], b1[2]);
                mma_bf(c[mi][3], a[cur][mi], b1[1], b1[3]);
            }
        }
    }

    // epilogue: dequant + store
#pragma unroll
    for (int mi = 0; mi < 4; mi++) {
        int row0 = m0 + m_off + mi * 16 + (l >> 2);
        float sl0 = g_sl[row0], sl1 = g_sl[row0 + 8];
        float* o0 = out + (size_t)row0 * DIM_N;
        float* o1 = out + (size_t)(row0 + 8) * DIM_N;
#pragma unroll
        for (int ni = 0; ni < 4; ni++) {
            int col = n0 + n_off + ni * 8 + (l & 3) * 2;
            float sr0 = col_scale(col), sr1 = col_scale(col + 1);
            float2 v0, v1;
            v0.x = c[mi][ni][0] * sl0 * sr0;
            v0.y = c[mi][ni][1] * sl0 * sr1;
            v1.x = c[mi][ni][2] * sl1 * sr0;
            v1.y = c[mi][ni][3] * sl1 * sr1;
            *reinterpret_cast<float2*>(o0 + col) = v0;
            *reinterpret_cast<float2*>(o1 + col) = v1;
        }
    }
}

// ---------------- launch ----------------
extern "C" void kernel_launch(void* const* d_in, const int* in_sizes, int n_in,
                              void* d_out, int out_size) {
    const float* lhs = (const float*)d_in[0];
    const float* rhs = (const float*)d_in[1];
    float* out = (float*)d_out;

    cudaFuncSetAttribute(k_gemm, cudaFuncAttributeMaxDynamicSharedMemorySize, SMEM_GEMM);

    k_quant_lhs<<<MR, 256>>>(lhs);
    k_rhs_amax<<<dim3(DIM_N / 256, DIM_K / 128), 256>>>(rhs);
    k_quant_rhs_t<<<dim3(DIM_N / 64, DIM_K / 64), 256>>>(rhs);
    k_gemm<<<dim3(DIM_N / BN, MR / BM), GT, SMEM_GEMM>>>(out);
}

// round 14
// speedup vs baseline: 1.0078x; 1.0078x over previous
#include <cuda_runtime.h>
#include <cuda_bf16.h>
#include <cstdint>

#define DIM_K 4096
#define DIM_N 4096
#define MR    8192

__device__ __nv_bfloat16 g_qab [(size_t)MR * DIM_K];     // bf16 quantized lhs [MR,K]
__device__ __nv_bfloat16 g_qbTb[(size_t)DIM_N * DIM_K];  // bf16 quantized rhs^T [N,K]
__device__ float    g_sl[MR];
__device__ unsigned g_amax[DIM_N];

// ---------------- helpers ----------------
__device__ __forceinline__ uint32_t smem_u32(const void* p) {
    uint32_t a;
    asm("{ .reg .u64 t; cvta.to.shared.u64 t, %1; cvt.u32.u64 %0, t; }" : "=r"(a) : "l"(p));
    return a;
}
__device__ __forceinline__ void cp16(uint32_t dst, const void* src) {
    asm volatile("cp.async.cg.shared.global [%0], [%1], 16;" :: "r"(dst), "l"(src) : "memory");
}
__device__ __forceinline__ void ldm_x4(uint32_t* r, uint32_t addr) {
    asm volatile("ldmatrix.sync.aligned.m8n8.x4.shared.b16 {%0,%1,%2,%3}, [%4];"
                 : "=r"(r[0]), "=r"(r[1]), "=r"(r[2]), "=r"(r[3]) : "r"(addr));
}
__device__ __forceinline__ void mma_bf(float* c, const uint32_t* a, uint32_t b0, uint32_t b1) {
    asm volatile("mma.sync.aligned.m16n8k16.row.col.f32.bf16.bf16.f32 "
                 "{%0,%1,%2,%3}, {%4,%5,%6,%7}, {%8,%9}, {%0,%1,%2,%3};"
                 : "+f"(c[0]), "+f"(c[1]), "+f"(c[2]), "+f"(c[3])
                 : "r"(a[0]), "r"(a[1]), "r"(a[2]), "r"(a[3]), "r"(b0), "r"(b1));
}
__device__ __forceinline__ float qv(float x, float sc) {
    return fminf(fmaxf(rintf(x / sc), -127.f), 127.f);
}
__device__ __forceinline__ float col_scale(int n) {
    float am = __uint_as_float(g_amax[n]);
    return (am > 0.f) ? (am / 127.f) : 1.f;
}

// ---------------- K1: quantize lhs rows -> bf16 ----------------
__global__ __launch_bounds__(256) void k_quant_lhs(const float* __restrict__ lhs) {
    int row = blockIdx.x;
    const float4* src = reinterpret_cast<const float4*>(lhs) + (size_t)row * (DIM_K / 4);
    int t = threadIdx.x;
    float4 v[4];
    float amax = 0.f;
#pragma unroll
    for (int j = 0; j < 4; j++) {
        v[j] = src[t + j * 256];
        amax = fmaxf(amax, fmaxf(fmaxf(fabsf(v[j].x), fabsf(v[j].y)),
                                 fmaxf(fabsf(v[j].z), fabsf(v[j].w))));
    }
#pragma unroll
    for (int o = 16; o > 0; o >>= 1)
        amax = fmaxf(amax, __shfl_xor_sync(0xffffffffu, amax, o));
    __shared__ float wmax[8];
    __shared__ float sres;
    if ((t & 31) == 0) wmax[t >> 5] = amax;
    __syncthreads();
    if (t == 0) {
        float m = wmax[0];
#pragma unroll
        for (int j = 1; j < 8; j++) m = fmaxf(m, wmax[j]);
        float sc = (m > 0.f) ? (m / 127.f) : 1.f;
        sres = sc;
        g_sl[row] = sc;
    }
    __syncthreads();
    float sc = sres;
    uint2* dst = reinterpret_cast<uint2*>(g_qab + (size_t)row * DIM_K);
#pragma unroll
    for (int j = 0; j < 4; j++) {
        __nv_bfloat162 h0 = __floats2bfloat162_rn(qv(v[j].x, sc), qv(v[j].y, sc));
        __nv_bfloat162 h1 = __floats2bfloat162_rn(qv(v[j].z, sc), qv(v[j].w, sc));
        uint2 u;
        u.x = *reinterpret_cast<unsigned*>(&h0);
        u.y = *reinterpret_cast<unsigned*>(&h1);
        dst[t + j * 256] = u;
    }
}

// ---------------- K2: rhs amax + transpose-quantize -> bf16 ----------------
__global__ __launch_bounds__(256) void k_rhs_amax(const float* __restrict__ rhs) {
    int n = blockIdx.x * 256 + threadIdx.x;
    int k0 = blockIdx.y * 128;
    const float* p = rhs + (size_t)k0 * DIM_N + n;
    float amax = 0.f;
#pragma unroll 4
    for (int kk = 0; kk < 128; kk++)
        amax = fmaxf(amax, fabsf(p[(size_t)kk * DIM_N]));
    atomicMax(&g_amax[n], __float_as_uint(amax));
}

__global__ __launch_bounds__(256) void k_quant_rhs_t(const float* __restrict__ rhs) {
    __shared__ float tile[64][65];
    int n0 = blockIdx.x * 64, k0 = blockIdx.y * 64;
    int t = threadIdx.x;
    int c = t & 63, r0 = t >> 6;
    float sc = col_scale(n0 + c);
#pragma unroll
    for (int e = 0; e < 16; e++) {
        int r = r0 + e * 4;
        float x = rhs[(size_t)(k0 + r) * DIM_N + n0 + c];
        tile[c][r] = qv(x, sc);
    }
    __syncthreads();
    int rn = t >> 2, c16 = t & 3;
    uint32_t pb[8];
#pragma unroll
    for (int g = 0; g < 8; g++) {
        __nv_bfloat162 h = __floats2bfloat162_rn(tile[rn][c16 * 16 + g * 2],
                                                 tile[rn][c16 * 16 + g * 2 + 1]);
        pb[g] = *reinterpret_cast<unsigned*>(&h);
    }
    __nv_bfloat16* db = g_qbTb + (size_t)(n0 + rn) * DIM_K + k0 + c16 * 16;
    uint4 w0, w1;
    w0.x = pb[0]; w0.y = pb[1]; w0.z = pb[2]; w0.w = pb[3];
    w1.x = pb[4]; w1.y = pb[5]; w1.z = pb[6]; w1.w = pb[7];
    *reinterpret_cast<uint4*>(db) = w0;
    *reinterpret_cast<uint4*>(db + 8) = w1;
}

// ---------------- K3: bf16 GEMM, 256x128 tile, 512 thr, pair-buffered ----------------
#define BM 256
#define BN 128
#define GT 512
#define ROWB 144
#define BKB 128
#define A_BYTES (BM * ROWB)
#define B_BYTES (BN * ROWB)
#define STAGE_BYTES (A_BYTES + B_BYTES)     // 55296
#define PAIR_BYTES (2 * STAGE_BYTES)        // 110592
#define SMEM_GEMM (2 * PAIR_BYTES)          // 221184
#define NPAIR (DIM_K * 2 / BKB / 2)         // 32 pairs of chunks

// load 2 consecutive K-chunks into a pair of stages
__device__ __forceinline__ void load_pair(uint32_t pbase, int t,
                                          const char* gA, const char* gB,
                                          size_t kByte) {
    const size_t rstride = (size_t)DIM_K * 2;
#pragma unroll
    for (int h = 0; h < 2; h++) {
        uint32_t sbase = pbase + h * STAGE_BYTES;
        size_t kb = kByte + (size_t)h * BKB;
#pragma unroll
        for (int j = 0; j < 4; j++) {
            int c = t + j * GT;
            int r = c >> 3, q = c & 7;
            cp16(sbase + r * ROWB + q * 16, gA + (size_t)r * rstride + kb + q * 16);
        }
#pragma unroll
        for (int j = 0; j < 2; j++) {
            int c = t + j * GT;
            int r = c >> 3, q = c & 7;
            cp16(sbase + A_BYTES + r * ROWB + q * 16, gB + (size_t)r * rstride + kb + q * 16);
        }
    }
}

__global__ __launch_bounds__(GT, 1) void k_gemm(float* __restrict__ out) {
    extern __shared__ __align__(128) uint8_t smem[];
    const uint32_t sb = smem_u32(smem);
    const int t = threadIdx.x;
    const int w = t >> 5, l = t & 31;
    const int n0 = blockIdx.x * BN;
    const int m0 = blockIdx.y * BM;
    const int wm = w & 3, wn = w >> 2;       // warp grid 4x4
    const int m_off = wm * 64, n_off = wn * 32;

    const char* gA = (const char*)(g_qab + (size_t)m0 * DIM_K);
    const char* gB = (const char*)(g_qbTb + (size_t)n0 * DIM_K);

    float c[4][4][4];                        // 64 accum regs
#pragma unroll
    for (int mi = 0; mi < 4; mi++)
#pragma unroll
        for (int ni = 0; ni < 4; ni++)
#pragma unroll
            for (int e = 0; e < 4; e++) c[mi][ni][e] = 0.f;

    const int lrow = (l & 7) + ((l >> 3) & 1) * 8;
    const int lcol = (l >> 4) * 16;
    const uint32_t aBase = (uint32_t)((m_off + lrow) * ROWB + lcol);
    const uint32_t bBase = (uint32_t)(A_BYTES + (n_off + lrow) * ROWB + lcol);

    // prologue: load pair 0
    load_pair(sb, t, gA, gB, 0);
    asm volatile("cp.async.commit_group;" ::: "memory");

    for (int j = 0; j < NPAIR; j++) {
        const int p = j & 1;
        asm volatile("cp.async.wait_group 0;" ::: "memory");
        __syncthreads();

        // immediately stream next pair into the buffer freed at pair j-1
        if (j + 1 < NPAIR) {
            load_pair(sb + (p ^ 1) * PAIR_BYTES, t, gA, gB,
                      (size_t)(j + 1) * (2 * BKB));
        }
        asm volatile("cp.async.commit_group;" ::: "memory");

        // compute the 2 chunks of this pair: 8 uninterrupted ks-steps
#pragma unroll
        for (int h = 0; h < 2; h++) {
            const uint32_t stA = sb + (uint32_t)(p * 2 + h) * STAGE_BYTES + aBase;
            const uint32_t stB = sb + (uint32_t)(p * 2 + h) * STAGE_BYTES + bBase;
#pragma unroll
            for (int ks = 0; ks < 4; ks++) {
                uint32_t a[4][4], b[2][4];
#pragma unroll
                for (int mi = 0; mi < 4; mi++)
                    ldm_x4(a[mi], stA + mi * (16 * ROWB) + ks * 32);
#pragma unroll
                for (int nj = 0; nj < 2; nj++)
                    ldm_x4(b[nj], stB + nj * (16 * ROWB) + ks * 32);
#pragma unroll
                for (int mi = 0; mi < 4; mi++) {
                    mma_bf(c[mi][0], a[mi], b[0][0], b[0][2]);
                    mma_bf(c[mi][1], a[mi], b[0][1], b[0][3]);
                    mma_bf(c[mi][2], a[mi], b[1][0], b[1][2]);
                    mma_bf(c[mi][3], a[mi], b[1][1], b[1][3]);
                }
            }
        }
    }

    // epilogue: dequant + store
#pragma unroll
    for (int mi = 0; mi < 4; mi++) {
        int row0 = m0 + m_off + mi * 16 + (l >> 2);
        float sl0 = g_sl[row0], sl1 = g_sl[row0 + 8];
        float* o0 = out + (size_t)row0 * DIM_N;
        float* o1 = out + (size_t)(row0 + 8) * DIM_N;
#pragma unroll
        for (int ni = 0; ni < 4; ni++) {
            int col = n0 + n_off + ni * 8 + (l & 3) * 2;
            float sr0 = col_scale(col), sr1 = col_scale(col + 1);
            float2 v0, v1;
            v0.x = c[mi][ni][0] * sl0 * sr0;
            v0.y = c[mi][ni][1] * sl0 * sr1;
            v1.x = c[mi][ni][2] * sl1 * sr0;
            v1.y = c[mi][ni][3] * sl1 * sr1;
            *reinterpret_cast<float2*>(o0 + col) = v0;
            *reinterpret_cast<float2*>(o1 + col) = v1;
        }
    }
}

// ---------------- launch ----------------
extern "C" void kernel_launch(void* const* d_in, const int* in_sizes, int n_in,
                              void* d_out, int out_size) {
    const float* lhs = (const float*)d_in[0];
    const float* rhs = (const float*)d_in[1];
    float* out = (float*)d_out;

    cudaFuncSetAttribute(k_gemm, cudaFuncAttributeMaxDynamicSharedMemorySize, SMEM_GEMM);

    k_quant_lhs<<<MR, 256>>>(lhs);
    k_rhs_amax<<<dim3(DIM_N / 256, DIM_K / 128), 256>>>(rhs);
    k_quant_rhs_t<<<dim3(DIM_N / 64, DIM_K / 64), 256>>>(rhs);
    k_gemm<<<dim3(DIM_N / BN, MR / BM), GT, SMEM_GEMM>>>(out);
}

// round 15
// speedup vs baseline: 1.0610x; 1.0527x over previous
#include <cuda_runtime.h>
#include <cuda_bf16.h>
#include <cstdint>

#define DIM_K 4096
#define DIM_N 4096
#define MR    8192

__device__ __nv_bfloat16 g_qab [(size_t)MR * DIM_K];     // bf16 quantized lhs [MR,K]
__device__ __nv_bfloat16 g_qbTb[(size_t)DIM_N * DIM_K];  // bf16 quantized rhs^T [N,K]
__device__ float    g_sl[MR];
__device__ unsigned g_amax[DIM_N];

// ---------------- helpers ----------------
__device__ __forceinline__ uint32_t smem_u32(const void* p) {
    uint32_t a;
    asm("{ .reg .u64 t; cvta.to.shared.u64 t, %1; cvt.u32.u64 %0, t; }" : "=r"(a) : "l"(p));
    return a;
}
__device__ __forceinline__ void cp16(uint32_t dst, const void* src) {
    asm volatile("cp.async.cg.shared.global [%0], [%1], 16;" :: "r"(dst), "l"(src) : "memory");
}
__device__ __forceinline__ void ldm_x4(uint32_t* r, uint32_t addr) {
    asm volatile("ldmatrix.sync.aligned.m8n8.x4.shared.b16 {%0,%1,%2,%3}, [%4];"
                 : "=r"(r[0]), "=r"(r[1]), "=r"(r[2]), "=r"(r[3]) : "r"(addr));
}
__device__ __forceinline__ void mma_bf(float* c, const uint32_t* a, uint32_t b0, uint32_t b1) {
    asm volatile("mma.sync.aligned.m16n8k16.row.col.f32.bf16.bf16.f32 "
                 "{%0,%1,%2,%3}, {%4,%5,%6,%7}, {%8,%9}, {%0,%1,%2,%3};"
                 : "+f"(c[0]), "+f"(c[1]), "+f"(c[2]), "+f"(c[3])
                 : "r"(a[0]), "r"(a[1]), "r"(a[2]), "r"(a[3]), "r"(b0), "r"(b1));
}
__device__ __forceinline__ float qv(float x, float sc) {
    return fminf(fmaxf(rintf(x / sc), -127.f), 127.f);
}
__device__ __forceinline__ float col_scale(int n) {
    float am = __uint_as_float(g_amax[n]);
    return (am > 0.f) ? (am / 127.f) : 1.f;
}

// ---------------- K1: fused lhs-quantize + rhs-amax (independent work, one launch) ----
// blocks [0, MR)            : quantize one lhs row each
// blocks [MR, MR + 2048)    : rhs column-amax over a 128-row k-slab each
#define AMAX_BLOCKS ((DIM_N / 256) * (DIM_K / 128))   // 16 * 32 = 512... computed below

__global__ __launch_bounds__(256) void k_prep1(const float* __restrict__ lhs,
                                               const float* __restrict__ rhs) {
    if (blockIdx.x >= MR) {
        // rhs amax part: 512 blocks -> (n-block 0..15, k-slab 0..31)
        int bid = blockIdx.x - MR;
        int n = (bid & 15) * 256 + threadIdx.x;
        int k0 = (bid >> 4) * 128;
        const float* p = rhs + (size_t)k0 * DIM_N + n;
        float amax = 0.f;
#pragma unroll 4
        for (int kk = 0; kk < 128; kk++)
            amax = fmaxf(amax, fabsf(p[(size_t)kk * DIM_N]));
        atomicMax(&g_amax[n], __float_as_uint(amax));
        return;
    }
    int row = blockIdx.x;
    const float4* src = reinterpret_cast<const float4*>(lhs) + (size_t)row * (DIM_K / 4);
    int t = threadIdx.x;
    float4 v[4];
    float amax = 0.f;
#pragma unroll
    for (int j = 0; j < 4; j++) {
        v[j] = src[t + j * 256];
        amax = fmaxf(amax, fmaxf(fmaxf(fabsf(v[j].x), fabsf(v[j].y)),
                                 fmaxf(fabsf(v[j].z), fabsf(v[j].w))));
    }
#pragma unroll
    for (int o = 16; o > 0; o >>= 1)
        amax = fmaxf(amax, __shfl_xor_sync(0xffffffffu, amax, o));
    __shared__ float wmax[8];
    __shared__ float sres;
    if ((t & 31) == 0) wmax[t >> 5] = amax;
    __syncthreads();
    if (t == 0) {
        float m = wmax[0];
#pragma unroll
        for (int j = 1; j < 8; j++) m = fmaxf(m, wmax[j]);
        float sc = (m > 0.f) ? (m / 127.f) : 1.f;
        sres = sc;
        g_sl[row] = sc;
    }
    __syncthreads();
    float sc = sres;
    uint2* dst = reinterpret_cast<uint2*>(g_qab + (size_t)row * DIM_K);
#pragma unroll
    for (int j = 0; j < 4; j++) {
        __nv_bfloat162 h0 = __floats2bfloat162_rn(qv(v[j].x, sc), qv(v[j].y, sc));
        __nv_bfloat162 h1 = __floats2bfloat162_rn(qv(v[j].z, sc), qv(v[j].w, sc));
        uint2 u;
        u.x = *reinterpret_cast<unsigned*>(&h0);
        u.y = *reinterpret_cast<unsigned*>(&h1);
        dst[t + j * 256] = u;
    }
}

// ---------------- K2: rhs transpose-quantize -> bf16 ----------------
__global__ __launch_bounds__(256) void k_quant_rhs_t(const float* __restrict__ rhs) {
    __shared__ float tile[64][65];
    int n0 = blockIdx.x * 64, k0 = blockIdx.y * 64;
    int t = threadIdx.x;
    int c = t & 63, r0 = t >> 6;
    float sc = col_scale(n0 + c);
#pragma unroll
    for (int e = 0; e < 16; e++) {
        int r = r0 + e * 4;
        float x = rhs[(size_t)(k0 + r) * DIM_N + n0 + c];
        tile[c][r] = qv(x, sc);
    }
    __syncthreads();
    int rn = t >> 2, c16 = t & 3;
    uint32_t pb[8];
#pragma unroll
    for (int g = 0; g < 8; g++) {
        __nv_bfloat162 h = __floats2bfloat162_rn(tile[rn][c16 * 16 + g * 2],
                                                 tile[rn][c16 * 16 + g * 2 + 1]);
        pb[g] = *reinterpret_cast<unsigned*>(&h);
    }
    __nv_bfloat16* db = g_qbTb + (size_t)(n0 + rn) * DIM_K + k0 + c16 * 16;
    uint4 w0, w1;
    w0.x = pb[0]; w0.y = pb[1]; w0.z = pb[2]; w0.w = pb[3];
    w1.x = pb[4]; w1.y = pb[5]; w1.z = pb[6]; w1.w = pb[7];
    *reinterpret_cast<uint4*>(db) = w0;
    *reinterpret_cast<uint4*>(db + 8) = w1;
}

// ---------------- K3: bf16 GEMM, 256x128 tile, 512 threads (R11 schedule) ----------------
#define BM 256
#define BN 128
#define GT 512
#define ROWB 144
#define BKB 128
#define STAGES 4
#define A_BYTES (BM * ROWB)
#define B_BYTES (BN * ROWB)
#define STAGE_BYTES (A_BYTES + B_BYTES)
#define SMEM_GEMM (STAGES * STAGE_BYTES)
#define NCHUNK (DIM_K * 2 / BKB)

__device__ __forceinline__ void load_stage(uint32_t sbase, int t,
                                           const char* gA, const char* gB,
                                           size_t kByte) {
    const size_t rstride = (size_t)DIM_K * 2;
#pragma unroll
    for (int j = 0; j < 4; j++) {
        int c = t + j * GT;
        int r = c >> 3, q = c & 7;
        cp16(sbase + r * ROWB + q * 16, gA + (size_t)r * rstride + kByte + q * 16);
    }
#pragma unroll
    for (int j = 0; j < 2; j++) {
        int c = t + j * GT;
        int r = c >> 3, q = c & 7;
        cp16(sbase + A_BYTES + r * ROWB + q * 16, gB + (size_t)r * rstride + kByte + q * 16);
    }
}

__global__ __launch_bounds__(GT, 1) void k_gemm(float* __restrict__ out) {
    extern __shared__ __align__(128) uint8_t smem[];
    const uint32_t sb = smem_u32(smem);
    const int t = threadIdx.x;
    const int w = t >> 5, l = t & 31;
    const int n0 = blockIdx.x * BN;
    const int m0 = blockIdx.y * BM;
    const int wm = w & 3, wn = w >> 2;       // warp grid 4x4
    const int m_off = wm * 64, n_off = wn * 32;

    const char* gA = (const char*)(g_qab + (size_t)m0 * DIM_K);
    const char* gB = (const char*)(g_qbTb + (size_t)n0 * DIM_K);

    float c[4][4][4];                        // 64 accum regs: 64(M) x 32(N)
#pragma unroll
    for (int mi = 0; mi < 4; mi++)
#pragma unroll
        for (int ni = 0; ni < 4; ni++)
#pragma unroll
            for (int e = 0; e < 4; e++) c[mi][ni][e] = 0.f;

    const int lrow = (l & 7) + ((l >> 3) & 1) * 8;
    const int lcol = (l >> 4) * 16;
    const uint32_t aBase = (uint32_t)((m_off + lrow) * ROWB + lcol);
    const uint32_t bBase = (uint32_t)(A_BYTES + (n_off + lrow) * ROWB + lcol);

#pragma unroll
    for (int p = 0; p < STAGES - 1; p++) {
        load_stage(sb + p * STAGE_BYTES, t, gA, gB, (size_t)p * BKB);
        asm volatile("cp.async.commit_group;" ::: "memory");
    }

    for (int i = 0; i < NCHUNK; i++) {
        asm volatile("cp.async.wait_group 2;" ::: "memory");
        __syncthreads();
        if (i + STAGES - 1 < NCHUNK)
            load_stage(sb + ((i + STAGES - 1) & 3) * STAGE_BYTES, t, gA, gB,
                       (size_t)(i + STAGES - 1) * BKB);
        asm volatile("cp.async.commit_group;" ::: "memory");

        const uint32_t stA = sb + (uint32_t)(i & 3) * STAGE_BYTES + aBase;
        const uint32_t stB = sb + (uint32_t)(i & 3) * STAGE_BYTES + bBase;

#pragma unroll
        for (int ks = 0; ks < 4; ks++) {
            uint32_t a[4][4], b[2][4];
#pragma unroll
            for (int mi = 0; mi < 4; mi++)
                ldm_x4(a[mi], stA + mi * (16 * ROWB) + ks * 32);
#pragma unroll
            for (int nj = 0; nj < 2; nj++)
                ldm_x4(b[nj], stB + nj * (16 * ROWB) + ks * 32);
#pragma unroll
            for (int mi = 0; mi < 4; mi++) {
                mma_bf(c[mi][0], a[mi], b[0][0], b[0][2]);
                mma_bf(c[mi][1], a[mi], b[0][1], b[0][3]);
                mma_bf(c[mi][2], a[mi], b[1][0], b[1][2]);
                mma_bf(c[mi][3], a[mi], b[1][1], b[1][3]);
            }
        }
    }

    // epilogue: dequant + store (sr scales hoisted out of mi loop)
    float sr0[4], sr1[4];
#pragma unroll
    for (int ni = 0; ni < 4; ni++) {
        int col = n0 + n_off + ni * 8 + (l & 3) * 2;
        sr0[ni] = col_scale(col);
        sr1[ni] = col_scale(col + 1);
    }
#pragma unroll
    for (int mi = 0; mi < 4; mi++) {
        int row0 = m0 + m_off + mi * 16 + (l >> 2);
        float sl0 = g_sl[row0], sl1 = g_sl[row0 + 8];
        float* o0 = out + (size_t)row0 * DIM_N;
        float* o1 = out + (size_t)(row0 + 8) * DIM_N;
#pragma unroll
        for (int ni = 0; ni < 4; ni++) {
            int col = n0 + n_off + ni * 8 + (l & 3) * 2;
            float2 v0, v1;
            v0.x = c[mi][ni][0] * sl0 * sr0[ni];
            v0.y = c[mi][ni][1] * sl0 * sr1[ni];
            v1.x = c[mi][ni][2] * sl1 * sr0[ni];
            v1.y = c[mi][ni][3] * sl1 * sr1[ni];
            *reinterpret_cast<float2*>(o0 + col) = v0;
            *reinterpret_cast<float2*>(o1 + col) = v1;
        }
    }
}

// ---------------- launch ----------------
extern "C" void kernel_launch(void* const* d_in, const int* in_sizes, int n_in,
                              void* d_out, int out_size) {
    const float* lhs = (const float*)d_in[0];
    const float* rhs = (const float*)d_in[1];
    float* out = (float*)d_out;

    cudaFuncSetAttribute(k_gemm, cudaFuncAttributeMaxDynamicSharedMemorySize, SMEM_GEMM);

    // fused: lhs quantize (blocks 0..MR-1) + rhs amax (blocks MR..MR+511)
    k_prep1<<<MR + (DIM_N / 256) * (DIM_K / 128), 256>>>(lhs, rhs);
    k_quant_rhs_t<<<dim3(DIM_N / 64, DIM_K / 64), 256>>>(rhs);
    k_gemm<<<dim3(DIM_N / BN, MR / BM), GT, SMEM_GEMM>>>(out);
}